// round 1
// baseline (speedup 1.0000x reference)
#include <cuda_runtime.h>
#include <cuda_bf16.h>

// CrossNet: B=500000 rows, D=128, L=4 layers.
// per layer: s = dot(xl, w_l)  (scalar per row);  xl = x0 * s + b_l + xl
// One warp per row: lane handles 4 contiguous floats (float4), so each warp's
// load/store is one fully coalesced 512B row. Weights/biases live in registers
// (16+16 floats per lane), loaded once from a 4KB L2-resident table.

#ifndef CN_L
#define CN_L 4
#endif
#define CN_D 128

__global__ __launch_bounds__(256) void crossnet_kernel(
    const float4* __restrict__ x,     // inputs  [B, 128] as float4 [B, 32]
    const float*  __restrict__ w,     // kernels [L, 128]
    const float*  __restrict__ b,     // biases  [L, 128]
    float4*       __restrict__ out,   // output  [B, 128] as float4 [B, 32]
    int B)
{
    const int warp = (blockIdx.x * blockDim.x + threadIdx.x) >> 5;
    const int lane = threadIdx.x & 31;
    if (warp >= B) return;

    // Per-lane slice of weights/biases for all layers (cache-hit loads).
    float4 wv[CN_L], bv[CN_L];
    const float4* w4 = reinterpret_cast<const float4*>(w);
    const float4* b4 = reinterpret_cast<const float4*>(b);
#pragma unroll
    for (int l = 0; l < CN_L; ++l) {
        wv[l] = __ldg(&w4[l * 32 + lane]);
        bv[l] = __ldg(&b4[l * 32 + lane]);
    }

    // Load this row (coalesced: 32 lanes x 16B = 512B contiguous).
    const float4 x0 = x[(size_t)warp * 32 + lane];
    float x0a[4] = {x0.x, x0.y, x0.z, x0.w};
    float xl[4]  = {x0.x, x0.y, x0.z, x0.w};

#pragma unroll
    for (int l = 0; l < CN_L; ++l) {
        // partial dot over this lane's 4 elements
        float p = xl[0] * wv[l].x;
        p = fmaf(xl[1], wv[l].y, p);
        p = fmaf(xl[2], wv[l].z, p);
        p = fmaf(xl[3], wv[l].w, p);
        // warp butterfly reduction -> full dot s in all lanes
#pragma unroll
        for (int off = 16; off > 0; off >>= 1)
            p += __shfl_xor_sync(0xffffffffu, p, off);
        // xl = x0 * s + b + xl
        const float bb[4] = {bv[l].x, bv[l].y, bv[l].z, bv[l].w};
#pragma unroll
        for (int j = 0; j < 4; ++j)
            xl[j] = fmaf(x0a[j], p, bb[j] + xl[j]);
    }

    float4 o;
    o.x = xl[0]; o.y = xl[1]; o.z = xl[2]; o.w = xl[3];
    out[(size_t)warp * 32 + lane] = o;
}

extern "C" void kernel_launch(void* const* d_in, const int* in_sizes, int n_in,
                              void* d_out, int out_size)
{
    const float* x = (const float*)d_in[0];   // inputs  [B,128]
    const float* w = (const float*)d_in[1];   // kernels [L,128,1]
    const float* b = (const float*)d_in[2];   // biases  [L,128,1]
    float* out = (float*)d_out;

    const int B = in_sizes[0] / CN_D;         // 500000
    const int rows_per_block = 256 / 32;      // 8
    const int grid = (B + rows_per_block - 1) / rows_per_block;

    crossnet_kernel<<<grid, 256>>>(
        reinterpret_cast<const float4*>(x), w, b,
        reinterpret_cast<float4*>(out), B);
}

// round 2
// speedup vs baseline: 1.0313x; 1.0313x over previous
#include <cuda_runtime.h>
#include <cuda_bf16.h>

// CrossNet: B=500000 rows, D=128, L=4 layers.
//   per layer: s = dot(xl, w_l);  xl = x0 * s + b_l + xl
//
// R2: one warp handles RPW=8 consecutive rows. Weights/biases are loaded into
// registers ONCE per warp (not per row), removing the L1tex wavefront pressure
// that bound R1 (L1=90.8%, DRAM=51%). Rows processed in pairs for ILP/MLP.

#define CN_L 4
#define CN_D 128
#define RPW  8   // rows per warp

__global__ __launch_bounds__(256) void crossnet_kernel(
    const float4* __restrict__ x,     // inputs  [B, 128] as float4 [B, 32]
    const float*  __restrict__ w,     // kernels [L, 128]
    const float*  __restrict__ b,     // biases  [L, 128]
    float4*       __restrict__ out,   // output  [B, 128] as float4 [B, 32]
    int B)
{
    const int warp = (blockIdx.x * blockDim.x + threadIdx.x) >> 5;
    const int lane = threadIdx.x & 31;
    const long long row0 = (long long)warp * RPW;
    if (row0 >= B) return;

    // Per-lane slice of weights/biases, loaded once per warp lifetime.
    float4 wv[CN_L], bv[CN_L];
    const float4* w4 = reinterpret_cast<const float4*>(w);
    const float4* b4 = reinterpret_cast<const float4*>(b);
#pragma unroll
    for (int l = 0; l < CN_L; ++l) {
        wv[l] = __ldg(&w4[l * 32 + lane]);
        bv[l] = __ldg(&b4[l * 32 + lane]);
    }

#pragma unroll
    for (int r = 0; r < RPW; r += 2) {
        const long long rowA = row0 + r;
        const long long rowB = rowA + 1;
        const bool okA = rowA < B;
        const bool okB = rowB < B;

        // Two independent row loads in flight (MLP=2).
        float4 a4 = okA ? x[rowA * 32 + lane] : make_float4(0.f, 0.f, 0.f, 0.f);
        float4 c4 = okB ? x[rowB * 32 + lane] : make_float4(0.f, 0.f, 0.f, 0.f);

        float xa[4] = {a4.x, a4.y, a4.z, a4.w};
        float la[4] = {a4.x, a4.y, a4.z, a4.w};
        float xb[4] = {c4.x, c4.y, c4.z, c4.w};
        float lb[4] = {c4.x, c4.y, c4.z, c4.w};

#pragma unroll
        for (int l = 0; l < CN_L; ++l) {
            // Partial dots for both rows (independent FMA chains).
            float pa = la[0] * wv[l].x;
            float pb = lb[0] * wv[l].x;
            pa = fmaf(la[1], wv[l].y, pa);
            pb = fmaf(lb[1], wv[l].y, pb);
            pa = fmaf(la[2], wv[l].z, pa);
            pb = fmaf(lb[2], wv[l].z, pb);
            pa = fmaf(la[3], wv[l].w, pa);
            pb = fmaf(lb[3], wv[l].w, pb);
            // Interleaved butterfly reductions (two independent SHFL chains).
#pragma unroll
            for (int off = 16; off > 0; off >>= 1) {
                pa += __shfl_xor_sync(0xffffffffu, pa, off);
                pb += __shfl_xor_sync(0xffffffffu, pb, off);
            }
#pragma unroll
            for (int j = 0; j < 4; ++j) {
                const float bbj = (j == 0) ? bv[l].x : (j == 1) ? bv[l].y
                                 : (j == 2) ? bv[l].z : bv[l].w;
                la[j] = fmaf(xa[j], pa, bbj + la[j]);
                lb[j] = fmaf(xb[j], pb, bbj + lb[j]);
            }
        }

        if (okA) {
            float4 o; o.x = la[0]; o.y = la[1]; o.z = la[2]; o.w = la[3];
            out[rowA * 32 + lane] = o;
        }
        if (okB) {
            float4 o; o.x = lb[0]; o.y = lb[1]; o.z = lb[2]; o.w = lb[3];
            out[rowB * 32 + lane] = o;
        }
    }
}

extern "C" void kernel_launch(void* const* d_in, const int* in_sizes, int n_in,
                              void* d_out, int out_size)
{
    const float* x = (const float*)d_in[0];   // inputs  [B,128]
    const float* w = (const float*)d_in[1];   // kernels [L,128,1]
    const float* b = (const float*)d_in[2];   // biases  [L,128,1]
    float* out = (float*)d_out;

    const int B = in_sizes[0] / CN_D;                 // 500000
    const int warps_needed = (B + RPW - 1) / RPW;     // 62500
    const int warps_per_block = 256 / 32;             // 8
    const int grid = (warps_needed + warps_per_block - 1) / warps_per_block;

    crossnet_kernel<<<grid, 256>>>(
        reinterpret_cast<const float4*>(x), w, b,
        reinterpret_cast<float4*>(out), B);
}

// round 3
// speedup vs baseline: 1.3177x; 1.2777x over previous
#include <cuda_runtime.h>
#include <cuda_bf16.h>

// CrossNet: B=500000, D=128, L=4.
//   layer: s = w_l·xl ; xl = x0*s + b_l + xl
//
// R3: algebraic form xl_i = alpha_i * x0 + beta_i, with beta_i = sum_{j<i} b_j
// (row-independent). Per row we need only d_l = w_l·x0 (4 PARALLEL dots of x0,
// one interleaved butterfly), then a 4-FMA scalar recurrence:
//   alpha_{l+1} = alpha_l*(1+d_l) + c_l,   c_l = w_l·beta_l  (row-independent)
//   out = alpha_L * x0 + beta_L
// This collapses the per-row serial chain from ~4x130cyc of dependent SHFL
// trees to a single 5-deep tree. 4 rows per warp, all loads issued upfront.

#define CN_L 4
#define CN_D 128
#define RPI  4   // rows per warp

__global__ __launch_bounds__(256) void crossnet_kernel(
    const float4* __restrict__ x,     // inputs  [B,128] as float4 [B,32]
    const float*  __restrict__ w,     // kernels [L,128]
    const float*  __restrict__ b,     // biases  [L,128]
    float4*       __restrict__ out,   // output
    int B)
{
    const int warp = (blockIdx.x * blockDim.x + threadIdx.x) >> 5;
    const int lane = threadIdx.x & 31;
    const long long row0 = (long long)warp * RPI;
    if (row0 >= B) return;

    const float4* w4 = reinterpret_cast<const float4*>(w);
    const float4* b4 = reinterpret_cast<const float4*>(b);

    // ---- once-per-warp prologue: weights, beta prefix, c_l ----
    float4 wv[CN_L];
#pragma unroll
    for (int l = 0; l < CN_L; ++l) wv[l] = __ldg(&w4[l * 32 + lane]);

    float4 beta = make_float4(0.f, 0.f, 0.f, 0.f);   // per-lane slice of beta_l
    float c[CN_L];
#pragma unroll
    for (int l = 0; l < CN_L; ++l) {
        // c_l = w_l · beta_l  (beta BEFORE adding b_l)
        float p = wv[l].x * beta.x;
        p = fmaf(wv[l].y, beta.y, p);
        p = fmaf(wv[l].z, beta.z, p);
        p = fmaf(wv[l].w, beta.w, p);
        c[l] = p;
        float4 bl = __ldg(&b4[l * 32 + lane]);
        beta.x += bl.x; beta.y += bl.y; beta.z += bl.z; beta.w += bl.w;
    }
    // reduce the 4 c_l partials across the warp (interleaved butterflies)
#pragma unroll
    for (int off = 16; off > 0; off >>= 1) {
#pragma unroll
        for (int l = 0; l < CN_L; ++l)
            c[l] += __shfl_xor_sync(0xffffffffu, c[l], off);
    }
    // beta now holds this lane's slice of beta_L (final bias accumulation)

    // ---- 4 rows: load all upfront (MLP=4), one butterfly phase, store ----
    float4 x0v[RPI];
    bool ok[RPI];
#pragma unroll
    for (int r = 0; r < RPI; ++r) {
        const long long row = row0 + r;
        ok[r] = row < B;
        x0v[r] = ok[r] ? __ldcs(&x[row * 32 + lane])
                       : make_float4(0.f, 0.f, 0.f, 0.f);
    }

    // partial dots d_l = w_l · x0  for each row, each layer (independent FMAs)
    float p[RPI][CN_L];
#pragma unroll
    for (int r = 0; r < RPI; ++r) {
#pragma unroll
        for (int l = 0; l < CN_L; ++l) {
            float q = wv[l].x * x0v[r].x;
            q = fmaf(wv[l].y, x0v[r].y, q);
            q = fmaf(wv[l].z, x0v[r].z, q);
            q = fmaf(wv[l].w, x0v[r].w, q);
            p[r][l] = q;
        }
    }
    // one interleaved butterfly pass: 16 independent chains, 5 deep
#pragma unroll
    for (int off = 16; off > 0; off >>= 1) {
#pragma unroll
        for (int r = 0; r < RPI; ++r)
#pragma unroll
            for (int l = 0; l < CN_L; ++l)
                p[r][l] += __shfl_xor_sync(0xffffffffu, p[r][l], off);
    }

    // scalar alpha recurrence + output
#pragma unroll
    for (int r = 0; r < RPI; ++r) {
        float a = 1.0f;
#pragma unroll
        for (int l = 0; l < CN_L; ++l)
            a = fmaf(a, p[r][l], a + c[l]);   // alpha*(1+d) + c
        if (ok[r]) {
            float4 o;
            o.x = fmaf(x0v[r].x, a, beta.x);
            o.y = fmaf(x0v[r].y, a, beta.y);
            o.z = fmaf(x0v[r].z, a, beta.z);
            o.w = fmaf(x0v[r].w, a, beta.w);
            __stcs(&out[(row0 + r) * 32 + lane], o);
        }
    }
}

extern "C" void kernel_launch(void* const* d_in, const int* in_sizes, int n_in,
                              void* d_out, int out_size)
{
    const float* x = (const float*)d_in[0];   // inputs  [B,128]
    const float* w = (const float*)d_in[1];   // kernels [L,128,1]
    const float* b = (const float*)d_in[2];   // biases  [L,128,1]
    float* out = (float*)d_out;

    const int B = in_sizes[0] / CN_D;                     // 500000
    const int warps_needed = (B + RPI - 1) / RPI;         // 125000
    const int warps_per_block = 256 / 32;                 // 8
    const int grid = (warps_needed + warps_per_block - 1) / warps_per_block;

    crossnet_kernel<<<grid, 256>>>(
        reinterpret_cast<const float4*>(x), w, b,
        reinterpret_cast<float4*>(out), B);
}